// round 11
// baseline (speedup 1.0000x reference)
#include <cuda_runtime.h>
#include <math.h>
#include <cooperative_groups.h>
#include <cooperative_groups/reduce.h>

namespace cg = cooperative_groups;

// SVRaster: 4096 rays vs 16^3 regular voxel grid on [-1,1]^3.
//
// ONE WARP PER RAY. Lane l = 2*j + h: slab j (traversal order along the
// dominant axis D), half h. Since |dU|,|dV| <= |dD| a slab has at most one
// U crossing and one V crossing => visited cells lie in {u0,u1} x {v0,v1}.
// Half 0 tests (u0,v0),(u1,v0); half 1 tests (u0,v1),(u1,v1). The two middle
// candidates are mutually exclusive, so lane order == exact tn order.
// All hit decisions use the EXACT reference slab arithmetic (planes
// i*0.125-1 are exact fp32 == ctr +/- half): hit set & order == reference.
// Compositing uses linearity in incoming transmittance: local composite with
// T=1, then a width-32 shuffle prefix-product supplies each lane's true T0.
// Hit placement via ballots; final sums via cg::reduce (REDUX.F32 path on
// Blackwell). Body templated on the dominant axis (warp-uniform branch).

#define GN       16
#define CELL     0.125f
#define BMIN     (-1.0f)
#define MAX_HITS 100
#define BLOCK    256

__device__ __forceinline__ float safe_dir(float d) {
    return (fabsf(d) < 1e-8f) ? ((d >= 0.0f) ? 1e-8f : -1e-8f) : d;
}

template<int AX>
__device__ __forceinline__ int voxi(int k, int u, int v) {
    if (AX == 0) return (k * GN + u) * GN + v;   // D=x, U=y, V=z
    if (AX == 1) return (u * GN + k) * GN + v;   // D=y, U=x, V=z
    return (u * GN + v) * GN + k;                // D=z, U=x, V=y
}

template<int AX>
__device__ __forceinline__ void trace_body(
    int lane, int r, int R,
    float oD, float oU, float oV,
    float iD, float iU, float iV,
    float dUr, float dVr,
    float tEnter, float tExit,
    const float* __restrict__ vdens,
    const float* __restrict__ vcol,
    float* __restrict__ out,
    float* __restrict__ out_idx)
{
    const unsigned FULL = 0xffffffffu;
    const int j = lane >> 1;
    const int h = lane & 1;

    const int sD = (iD >= 0.0f) ? 1 : -1;
    const int sU = (iU >= 0.0f) ? 1 : -1;
    const int sV = (iV >= 0.0f) ? 1 : -1;
    const int exU = (sU > 0) ? 1 : 0;
    const int exV = (sV > 0) ? 1 : 0;

    // Slab j -> grid layer k in traversal order.
    const int k = (sD > 0) ? j : (GN - 1 - j);

    // Exact D-axis crossings of slab k.
    float pk0 = fmaf((float)k,       CELL, BMIN);
    float pk1 = fmaf((float)(k + 1), CELL, BMIN);
    float tA = (pk0 - oD) * iD;
    float tB = (pk1 - oD) * iD;
    float lDk = fminf(tA, tB);
    float nDk = fmaxf(tA, tB);
    float lD0 = fmaxf(lDk, 0.0f);

    float w0 = fmaxf(lDk, tEnter);
    float w1 = fminf(nDk, tExit);
    bool alive = (w1 > w0);

    // ---- U axis: entry cell u0 (exact-crossing corrected) + exit cell u1 ----
    float pu = fmaf(dUr, w0, oU);
    int u0 = (int)floorf((pu - BMIN) * 8.0f);
    float lu0 = (fmaf((float)(u0 + 1 - exU), CELL, BMIN) - oU) * iU;
    float nu0 = (fmaf((float)(u0 + exU),     CELL, BMIN) - oU) * iU;
    if      (nu0 < w0) u0 += sU;       // floor undershot
    else if (lu0 > w0) u0 -= sU;       // floor overshot
    lu0 = (fmaf((float)(u0 + 1 - exU), CELL, BMIN) - oU) * iU;
    nu0 = (fmaf((float)(u0 + exU),     CELL, BMIN) - oU) * iU;
    bool stepU = (nu0 < w1);
    int   u1  = u0 + (stepU ? sU : 0);
    float lu1 = stepU ? nu0 : lu0;
    float nu1 = stepU ? ((fmaf((float)(u1 + exU), CELL, BMIN) - oU) * iU) : nu0;

    // ---- V axis ----
    float pv = fmaf(dVr, w0, oV);
    int v0 = (int)floorf((pv - BMIN) * 8.0f);
    float lv0 = (fmaf((float)(v0 + 1 - exV), CELL, BMIN) - oV) * iV;
    float nv0 = (fmaf((float)(v0 + exV),     CELL, BMIN) - oV) * iV;
    if      (nv0 < w0) v0 += sV;
    else if (lv0 > w0) v0 -= sV;
    lv0 = (fmaf((float)(v0 + 1 - exV), CELL, BMIN) - oV) * iV;
    nv0 = (fmaf((float)(v0 + exV),     CELL, BMIN) - oV) * iV;
    bool stepV = (nv0 < w1);
    int   v1  = v0 + (stepV ? sV : 0);
    float lv1 = stepV ? nv0 : lv0;
    float nv1 = stepV ? ((fmaf((float)(v1 + exV), CELL, BMIN) - oV) * iV) : nv0;

    // ---- this lane's V row: half 0 -> v0, half 1 -> v1 ----
    int   vH  = h ? v1  : v0;
    float lvH = h ? lv1 : lv0;
    float nvH = h ? nv1 : nv0;
    bool gateH = h ? stepV : true;      // half 1 only exists if V stepped
    bool inbVH = ((unsigned)vH < GN);
    bool inbU0 = ((unsigned)u0 < GN), inbU1 = ((unsigned)u1 < GN);

    // ---- two candidates: (u0, vH) then (u1, vH), exact slab arithmetic ----
    float tnA = fmaxf(fmaxf(lu0, lvH), lD0), tfA = fminf(fminf(nu0, nvH), nDk);
    float tnB = fmaxf(fmaxf(lu1, lvH), lD0), tfB = fminf(fminf(nu1, nvH), nDk);
    bool hitA = alive && gateH && inbU0 && inbVH && (tfA > tnA);
    bool hitB = alive && gateH && stepU && inbU1 && inbVH && (tfB > tnB);

    // Clamped indices for safe unconditional loads.
    int uc0 = min(GN - 1, max(0, u0)), uc1 = min(GN - 1, max(0, u1));
    int vcH = min(GN - 1, max(0, vH));
    int voxA = voxi<AX>(k, uc0, vcH);
    int voxB = voxi<AX>(k, uc1, vcH);

    // Unconditional loads (all L1-resident), gated composite.
    float sgA = __expf(__ldg(&vdens[voxA]));
    float aA0 = __ldg(&vcol[3 * voxA + 0]);
    float aA1 = __ldg(&vcol[3 * voxA + 1]);
    float aA2 = __ldg(&vcol[3 * voxA + 2]);
    float sgB = __expf(__ldg(&vdens[voxB]));
    float aB0 = __ldg(&vcol[3 * voxB + 0]);
    float aB1 = __ldg(&vcol[3 * voxB + 1]);
    float aB2 = __ldg(&vcol[3 * voxB + 2]);

    float alA = 1.0f - __expf(-sgA * (tfA - tnA));
    float alB = 1.0f - __expf(-sgB * (tfB - tnB));

    float Tl = 1.0f, lr = 0.0f, lg = 0.0f, lb = 0.0f, ldep = 0.0f;
    {
        float w = hitA ? alA : 0.0f;              // Tl == 1 here
        lr   = fmaf(w, aA0, lr);
        lg   = fmaf(w, aA1, lg);
        lb   = fmaf(w, aA2, lb);
        ldep = fmaf(w, tnA + tfA, ldep);          // x2 depth; scaled at end
        Tl   = hitA ? (1.0f - alA + 1e-10f) : 1.0f;
    }
    {
        float w = hitB ? (Tl * alB) : 0.0f;
        lr   = fmaf(w, aB0, lr);
        lg   = fmaf(w, aB1, lg);
        lb   = fmaf(w, aB2, lb);
        ldep = fmaf(w, tnB + tfB, ldep);
        Tl  *= hitB ? (1.0f - alB + 1e-10f) : 1.0f;
    }

    // ---- ballots: hit order is (lane, A, B) -> base via popc below-mask ----
    unsigned mA = __ballot_sync(FULL, hitA);
    unsigned mB = __ballot_sync(FULL, hitB);
    unsigned below = (1u << lane) - 1u;
    int base  = __popc(mA & below) + __popc(mB & below);
    int total = __popc(mA) + __popc(mB);

    // ---- transmittance prefix product (width-32 shuffle scan) ----
    float prod = Tl;
    #pragma unroll
    for (int d = 1; d < 32; d <<= 1) {
        float p = __shfl_up_sync(FULL, prod, d);
        if (lane >= d) prod *= p;
    }
    float T0s = __shfl_up_sync(FULL, prod, 1);
    float T0 = lane ? T0s : 1.0f;

    // ---- reductions via cg::reduce (REDUX.F32.ADD path on Blackwell) ----
    auto warp = cg::tiled_partition<32>(cg::this_thread_block());
    float sr  = cg::reduce(warp, T0 * lr,   cg::plus<float>());
    float sg2 = cg::reduce(warp, T0 * lg,   cg::plus<float>());
    float sb  = cg::reduce(warp, T0 * lb,   cg::plus<float>());
    float sd  = cg::reduce(warp, T0 * ldep, cg::plus<float>());

    // ---- outputs ----
    __syncwarp(FULL);   // zero-fill (other lanes) before hit overwrites

    int p = base;
    if (hitA) out_idx[p++] = (float)voxA;
    if (hitB) out_idx[p]   = (float)voxB;

    if (lane == 0) {
        out[3 * r + 0] = sr;
        out[3 * r + 1] = sg2;
        out[3 * r + 2] = sb;
        out[(size_t)3 * R + r] = 0.5f * sd;       // exact binary rescale
        out[(size_t)4 * R + r] = (float)total;
    }
}

__global__ void __launch_bounds__(BLOCK)
svraster_kernel(const float* __restrict__ ro,
                const float* __restrict__ rd,
                const float* __restrict__ vdens,
                const float* __restrict__ vcol,
                float* __restrict__ out,
                int R)
{
    const int tid  = threadIdx.x;
    const int lane = tid & 31;
    const int r    = (blockIdx.x * BLOCK + tid) >> 5;   // ray id (1 warp/ray)

    const float ox = ro[3 * r + 0], oy = ro[3 * r + 1], oz = ro[3 * r + 2];
    const float dxr = rd[3 * r + 0], dyr = rd[3 * r + 1], dzr = rd[3 * r + 2];

    const float ivx = 1.0f / safe_dir(dxr);
    const float ivy = 1.0f / safe_dir(dyr);
    const float ivz = 1.0f / safe_dir(dzr);

    // Scene-box slab (exact same planes as grid faces).
    float tx0 = (BMIN - ox) * ivx, tx1 = (1.0f - ox) * ivx;
    float ty0 = (BMIN - oy) * ivy, ty1 = (1.0f - oy) * ivy;
    float tz0 = (BMIN - oz) * ivz, tz1 = (1.0f - oz) * ivz;
    float tEnter = fmaxf(fmaxf(fminf(tx0, tx1), fminf(ty0, ty1)), fminf(tz0, tz1));
    float tExit  = fminf(fminf(fmaxf(tx0, tx1), fmaxf(ty0, ty1)), fmaxf(tz0, tz1));
    tEnter = fmaxf(tEnter, 0.0f);

    // Early zero-fill of idx row (stores retire under the compute shadow).
    float* out_idx = out + (size_t)5 * R + (size_t)r * MAX_HITS;
    if (lane < MAX_HITS / 4)
        ((float4*)out_idx)[lane] = make_float4(0.0f, 0.0f, 0.0f, 0.0f);

    // Dominant axis D = argmax |d| (warp-uniform -> uniform branch dispatch).
    float adx = fabsf(dxr), ady = fabsf(dyr), adz = fabsf(dzr);
    if (adx >= ady && adx >= adz) {
        trace_body<0>(lane, r, R, ox, oy, oz, ivx, ivy, ivz, dyr, dzr,
                      tEnter, tExit, vdens, vcol, out, out_idx);
    } else if (ady >= adz) {
        trace_body<1>(lane, r, R, oy, ox, oz, ivy, ivx, ivz, dxr, dzr,
                      tEnter, tExit, vdens, vcol, out, out_idx);
    } else {
        trace_body<2>(lane, r, R, oz, ox, oy, ivz, ivx, ivy, dxr, dyr,
                      tEnter, tExit, vdens, vcol, out, out_idx);
    }
}

extern "C" void kernel_launch(void* const* d_in, const int* in_sizes, int n_in,
                              void* d_out, int out_size)
{
    const float* ro    = (const float*)d_in[0];
    const float* rd    = (const float*)d_in[1];
    const float* vdens = (const float*)d_in[4];
    const float* vcol  = (const float*)d_in[5];
    float* out = (float*)d_out;

    int R = in_sizes[0] / 3;
    long long total_threads = (long long)R * 32;
    int blocks = (int)((total_threads + BLOCK - 1) / BLOCK);
    svraster_kernel<<<blocks, BLOCK>>>(ro, rd, vdens, vcol, out, R);
}

// round 12
// speedup vs baseline: 1.3204x; 1.3204x over previous
#include <cuda_runtime.h>
#include <math.h>
#include <cooperative_groups.h>
#include <cooperative_groups/reduce.h>

namespace cg = cooperative_groups;

// SVRaster: 4096 rays vs 16^3 regular voxel grid on [-1,1]^3.
//
// ONE WARP PER RAY. Lane l = 2*j + h: slab j (traversal order along the
// dominant axis D), half h. Since |dU|,|dV| <= |dD| a slab has at most one
// U crossing and one V crossing => visited cells lie in {u0,u1} x {v0,v1}.
// Half 0 tests (u0,v0),(u1,v0); half 1 tests (u0,v1),(u1,v1). The two middle
// candidates are mutually exclusive, so lane order == exact tn order.
// All hit decisions use the EXACT reference slab arithmetic (planes
// i*0.125-1 are exact fp32 == ctr +/- half): hit set & order == reference.
// Compositing uses linearity in incoming transmittance: local composite with
// T=1, then an EXCLUSIVE width-32 shuffle prefix-product supplies each
// lane's true incoming T0. Hit placement via ballots; final sums via
// cg::reduce (REDUX.F32 path). Body templated on the dominant axis.

#define GN       16
#define CELL     0.125f
#define BMIN     (-1.0f)
#define MAX_HITS 100
#define BLOCK    128

__device__ __forceinline__ float safe_dir(float d) {
    return (fabsf(d) < 1e-8f) ? ((d >= 0.0f) ? 1e-8f : -1e-8f) : d;
}

template<int AX>
__device__ __forceinline__ int voxi(int k, int u, int v) {
    if (AX == 0) return (k * GN + u) * GN + v;   // D=x, U=y, V=z
    if (AX == 1) return (u * GN + k) * GN + v;   // D=y, U=x, V=z
    return (u * GN + v) * GN + k;                // D=z, U=x, V=y
}

template<int AX>
__device__ __forceinline__ void trace_body(
    int lane, int r, int R,
    float oD, float oU, float oV,
    float iD, float iU, float iV,
    float dUr, float dVr,
    float tEnter, float tExit,
    const float* __restrict__ vdens,
    const float* __restrict__ vcol,
    float* __restrict__ out,
    float* __restrict__ out_idx)
{
    const unsigned FULL = 0xffffffffu;
    const int j = lane >> 1;
    const int h = lane & 1;

    const int sD = (iD >= 0.0f) ? 1 : -1;
    const int sU = (iU >= 0.0f) ? 1 : -1;
    const int sV = (iV >= 0.0f) ? 1 : -1;
    const int exU = (sU > 0) ? 1 : 0;
    const int exV = (sV > 0) ? 1 : 0;

    // Slab j -> grid layer k in traversal order.
    const int k = (sD > 0) ? j : (GN - 1 - j);

    // Exact D-axis crossings of slab k.
    float pk0 = fmaf((float)k,       CELL, BMIN);
    float pk1 = fmaf((float)(k + 1), CELL, BMIN);
    float tA = (pk0 - oD) * iD;
    float tB = (pk1 - oD) * iD;
    float lDk = fminf(tA, tB);
    float nDk = fmaxf(tA, tB);
    float lD0 = fmaxf(lDk, 0.0f);

    float w0 = fmaxf(lDk, tEnter);
    float w1 = fminf(nDk, tExit);
    bool alive = (w1 > w0);

    // ---- U axis: entry cell u0 (exact-crossing corrected) + exit cell u1 ----
    float pu = fmaf(dUr, w0, oU);
    int u0 = (int)floorf((pu - BMIN) * 8.0f);
    float lu0 = (fmaf((float)(u0 + 1 - exU), CELL, BMIN) - oU) * iU;
    float nu0 = (fmaf((float)(u0 + exU),     CELL, BMIN) - oU) * iU;
    if      (nu0 < w0) u0 += sU;       // floor undershot
    else if (lu0 > w0) u0 -= sU;       // floor overshot
    lu0 = (fmaf((float)(u0 + 1 - exU), CELL, BMIN) - oU) * iU;
    nu0 = (fmaf((float)(u0 + exU),     CELL, BMIN) - oU) * iU;
    bool stepU = (nu0 < w1);
    int   u1  = u0 + (stepU ? sU : 0);
    float lu1 = stepU ? nu0 : lu0;
    float nu1 = stepU ? ((fmaf((float)(u1 + exU), CELL, BMIN) - oU) * iU) : nu0;

    // ---- V axis ----
    float pv = fmaf(dVr, w0, oV);
    int v0 = (int)floorf((pv - BMIN) * 8.0f);
    float lv0 = (fmaf((float)(v0 + 1 - exV), CELL, BMIN) - oV) * iV;
    float nv0 = (fmaf((float)(v0 + exV),     CELL, BMIN) - oV) * iV;
    if      (nv0 < w0) v0 += sV;
    else if (lv0 > w0) v0 -= sV;
    lv0 = (fmaf((float)(v0 + 1 - exV), CELL, BMIN) - oV) * iV;
    nv0 = (fmaf((float)(v0 + exV),     CELL, BMIN) - oV) * iV;
    bool stepV = (nv0 < w1);
    int   v1  = v0 + (stepV ? sV : 0);
    float lv1 = stepV ? nv0 : lv0;
    float nv1 = stepV ? ((fmaf((float)(v1 + exV), CELL, BMIN) - oV) * iV) : nv0;

    // ---- this lane's V row: half 0 -> v0, half 1 -> v1 ----
    int   vH  = h ? v1  : v0;
    float lvH = h ? lv1 : lv0;
    float nvH = h ? nv1 : nv0;
    bool gateH = h ? stepV : true;      // half 1 only exists if V stepped
    bool inbVH = ((unsigned)vH < GN);
    bool inbU0 = ((unsigned)u0 < GN), inbU1 = ((unsigned)u1 < GN);

    // ---- two candidates: (u0, vH) then (u1, vH), exact slab arithmetic ----
    float tnA = fmaxf(fmaxf(lu0, lvH), lD0), tfA = fminf(fminf(nu0, nvH), nDk);
    float tnB = fmaxf(fmaxf(lu1, lvH), lD0), tfB = fminf(fminf(nu1, nvH), nDk);
    bool hitA = alive && gateH && inbU0 && inbVH && (tfA > tnA);
    bool hitB = alive && gateH && stepU && inbU1 && inbVH && (tfB > tnB);

    // Clamped indices for safe unconditional loads.
    int uc0 = min(GN - 1, max(0, u0)), uc1 = min(GN - 1, max(0, u1));
    int vcH = min(GN - 1, max(0, vH));
    int voxA = voxi<AX>(k, uc0, vcH);
    int voxB = voxi<AX>(k, uc1, vcH);

    // Unconditional loads (all L1-resident), gated composite.
    float sgA = __expf(__ldg(&vdens[voxA]));
    float aA0 = __ldg(&vcol[3 * voxA + 0]);
    float aA1 = __ldg(&vcol[3 * voxA + 1]);
    float aA2 = __ldg(&vcol[3 * voxA + 2]);
    float sgB = __expf(__ldg(&vdens[voxB]));
    float aB0 = __ldg(&vcol[3 * voxB + 0]);
    float aB1 = __ldg(&vcol[3 * voxB + 1]);
    float aB2 = __ldg(&vcol[3 * voxB + 2]);

    float alA = 1.0f - __expf(-sgA * (tfA - tnA));
    float alB = 1.0f - __expf(-sgB * (tfB - tnB));

    float Tl = 1.0f, lr = 0.0f, lg = 0.0f, lb = 0.0f, ldep = 0.0f;
    {
        float w = hitA ? alA : 0.0f;              // Tl == 1 here
        lr   = fmaf(w, aA0, lr);
        lg   = fmaf(w, aA1, lg);
        lb   = fmaf(w, aA2, lb);
        ldep = fmaf(w, tnA + tfA, ldep);          // x2 depth; scaled at end
        Tl   = hitA ? (1.0f - alA + 1e-10f) : 1.0f;
    }
    {
        float w = hitB ? (Tl * alB) : 0.0f;
        lr   = fmaf(w, aB0, lr);
        lg   = fmaf(w, aB1, lg);
        lb   = fmaf(w, aB2, lb);
        ldep = fmaf(w, tnB + tfB, ldep);
        Tl  *= hitB ? (1.0f - alB + 1e-10f) : 1.0f;
    }

    // ---- ballots: hit order is (lane, A, B) -> base via popc below-mask ----
    unsigned mA = __ballot_sync(FULL, hitA);
    unsigned mB = __ballot_sync(FULL, hitB);
    unsigned below = (1u << lane) - 1u;
    int base  = __popc(mA & below) + __popc(mB & below);
    int total = __popc(mA) + __popc(mB);

    // ---- EXCLUSIVE transmittance prefix product (shift first, then scan) ----
    float T0 = __shfl_up_sync(FULL, Tl, 1);
    if (lane == 0) T0 = 1.0f;
    #pragma unroll
    for (int d = 1; d < 32; d <<= 1) {
        float p = __shfl_up_sync(FULL, T0, d);
        if (lane >= d) T0 *= p;
    }

    // ---- reductions via cg::reduce (REDUX.F32.ADD path) ----
    auto warp = cg::tiled_partition<32>(cg::this_thread_block());
    float sr  = cg::reduce(warp, T0 * lr,   cg::plus<float>());
    float sg2 = cg::reduce(warp, T0 * lg,   cg::plus<float>());
    float sb  = cg::reduce(warp, T0 * lb,   cg::plus<float>());
    float sd  = cg::reduce(warp, T0 * ldep, cg::plus<float>());

    // ---- outputs ----
    if (lane == 0) {
        out[3 * r + 0] = sr;
        out[3 * r + 1] = sg2;
        out[3 * r + 2] = sb;
        out[(size_t)3 * R + r] = 0.5f * sd;       // exact binary rescale
        out[(size_t)4 * R + r] = (float)total;
    }

    __syncwarp(FULL);   // zero-fill (other lanes) before hit overwrites

    int p = base;
    if (hitA) out_idx[p++] = (float)voxA;
    if (hitB) out_idx[p]   = (float)voxB;
}

__global__ void __launch_bounds__(BLOCK)
svraster_kernel(const float* __restrict__ ro,
                const float* __restrict__ rd,
                const float* __restrict__ vdens,
                const float* __restrict__ vcol,
                float* __restrict__ out,
                int R)
{
    const int tid  = threadIdx.x;
    const int lane = tid & 31;
    const int r    = (blockIdx.x * BLOCK + tid) >> 5;   // ray id (1 warp/ray)

    const float ox = ro[3 * r + 0], oy = ro[3 * r + 1], oz = ro[3 * r + 2];
    const float dxr = rd[3 * r + 0], dyr = rd[3 * r + 1], dzr = rd[3 * r + 2];

    const float ivx = 1.0f / safe_dir(dxr);
    const float ivy = 1.0f / safe_dir(dyr);
    const float ivz = 1.0f / safe_dir(dzr);

    // Scene-box slab (exact same planes as grid faces).
    float tx0 = (BMIN - ox) * ivx, tx1 = (1.0f - ox) * ivx;
    float ty0 = (BMIN - oy) * ivy, ty1 = (1.0f - oy) * ivy;
    float tz0 = (BMIN - oz) * ivz, tz1 = (1.0f - oz) * ivz;
    float tEnter = fmaxf(fmaxf(fminf(tx0, tx1), fminf(ty0, ty1)), fminf(tz0, tz1));
    float tExit  = fminf(fminf(fmaxf(tx0, tx1), fmaxf(ty0, ty1)), fmaxf(tz0, tz1));
    tEnter = fmaxf(tEnter, 0.0f);

    // Early zero-fill of idx row (stores retire under the compute shadow).
    float* out_idx = out + (size_t)5 * R + (size_t)r * MAX_HITS;
    if (lane < MAX_HITS / 4)
        ((float4*)out_idx)[lane] = make_float4(0.0f, 0.0f, 0.0f, 0.0f);

    // Dominant axis D = argmax |d| (warp-uniform -> uniform branch dispatch).
    float adx = fabsf(dxr), ady = fabsf(dyr), adz = fabsf(dzr);
    if (adx >= ady && adx >= adz) {
        trace_body<0>(lane, r, R, ox, oy, oz, ivx, ivy, ivz, dyr, dzr,
                      tEnter, tExit, vdens, vcol, out, out_idx);
    } else if (ady >= adz) {
        trace_body<1>(lane, r, R, oy, ox, oz, ivy, ivx, ivz, dxr, dzr,
                      tEnter, tExit, vdens, vcol, out, out_idx);
    } else {
        trace_body<2>(lane, r, R, oz, ox, oy, ivz, ivx, ivy, dxr, dyr,
                      tEnter, tExit, vdens, vcol, out, out_idx);
    }
}

extern "C" void kernel_launch(void* const* d_in, const int* in_sizes, int n_in,
                              void* d_out, int out_size)
{
    const float* ro    = (const float*)d_in[0];
    const float* rd    = (const float*)d_in[1];
    const float* vdens = (const float*)d_in[4];
    const float* vcol  = (const float*)d_in[5];
    float* out = (float*)d_out;

    int R = in_sizes[0] / 3;
    long long total_threads = (long long)R * 32;
    int blocks = (int)((total_threads + BLOCK - 1) / BLOCK);
    svraster_kernel<<<blocks, BLOCK>>>(ro, rd, vdens, vcol, out, R);
}